// round 15
// baseline (speedup 1.0000x reference)
#include <cuda_runtime.h>
#include <cuda_fp16.h>
#include <math.h>
#include <stdint.h>

#define B_SZ 512
#define D_SZ 512
#define C_SZ 100000
#define BN 128
#define BM 128
#define BK 64
#define NK 8                       // 512/64
#define NSTAGE 3
#define NSTRIPE 37
#define NTILES_N 782               // ceil(100000/128)
#define C_PAD (NTILES_N * BN)      // 100096
#define PITCH 72                   // halves per smem row (144 B)
#define STAGE_B (2 * 128 * PITCH * 2)      // 36864
#define B_PART  (128 * PITCH * 2)          // 18432
#define WINV_OFF (NSTAGE * STAGE_B)        // 110592
#define SMEM_BYTES (WINV_OFF + BN * 4)     // 111104
#define S_SCALE 30.0f
#define LMAX 31.0f
#define COS_M 0.8775825618903728f
#define SIN_M 0.47942553860420300f

// ---------------- static device scratch -------------------------------------
__device__ __half g_wh[(size_t)C_PAD * D_SZ];   // raw fp16 w (written per launch)
__device__ float g_winv[C_PAD];                 // 30/||w||, 0 for pads
__device__ int   g_flags[NTILES_N];             // quarters-converted count
__device__ __half g_xh[B_SZ * D_SZ];
__device__ float g_xn[B_SZ * D_SZ];
__device__ float g_rowsum[B_SZ];

// ---------------- PTX helpers ------------------------------------------------
__device__ __forceinline__ uint32_t smem_u32(const void* p) {
    uint32_t a;
    asm("{ .reg .u64 t; cvta.to.shared.u64 t, %1; cvt.u32.u64 %0, t; }" : "=r"(a) : "l"(p));
    return a;
}
__device__ __forceinline__ void cp16(uint32_t dst, const void* src) {
    asm volatile("cp.async.cg.shared.global [%0], [%1], 16;" :: "r"(dst), "l"(src));
}
#define CP_COMMIT() asm volatile("cp.async.commit_group;" ::: "memory")
#define CP_WAIT(n)  asm volatile("cp.async.wait_group %0;" :: "n"(n) : "memory")

__device__ __forceinline__ void ldsm4(uint32_t* r, uint32_t addr) {
    asm volatile("ldmatrix.sync.aligned.m8n8.x4.shared.b16 {%0,%1,%2,%3}, [%4];"
        : "=r"(r[0]), "=r"(r[1]), "=r"(r[2]), "=r"(r[3]) : "r"(addr));
}
__device__ __forceinline__ void mma16816h(uint32_t* d, const uint32_t* a, uint32_t b0, uint32_t b1) {
    asm volatile(
        "mma.sync.aligned.m16n8k16.row.col.f16.f16.f16.f16 "
        "{%0,%1}, {%2,%3,%4,%5}, {%6,%7}, {%0,%1};"
        : "+r"(d[0]), "+r"(d[1])
        : "r"(a[0]), "r"(a[1]), "r"(a[2]), "r"(a[3]), "r"(b0), "r"(b1));
}
__device__ __forceinline__ uint2 pack4h(float4 v) {
    __half2 h0 = __floats2half2_rn(v.x, v.y);
    __half2 h1 = __floats2half2_rn(v.z, v.w);
    uint2 o;
    o.x = *reinterpret_cast<uint32_t*>(&h0);
    o.y = *reinterpret_cast<uint32_t*>(&h1);
    return o;
}

// ---------------------------------------------------------------------------
// Kernel 1: normalize x rows; zero g_rowsum, g_flags, out.
// ---------------------------------------------------------------------------
__global__ void xnorm_kernel(const float* __restrict__ x, float* __restrict__ out) {
    const int row = blockIdx.x;
    const int tid = threadIdx.x;   // 128
    const float* xr = x + (size_t)row * D_SZ;

    float ss = 0.f;
    float v[4];
    #pragma unroll
    for (int i = 0; i < 4; i++) { v[i] = xr[tid + i * 128]; ss += v[i] * v[i]; }
    __shared__ float red[128];
    red[tid] = ss;
    __syncthreads();
    #pragma unroll
    for (int off = 64; off > 0; off >>= 1) {
        if (tid < off) red[tid] += red[tid + off];
        __syncthreads();
    }
    const float inv = 1.f / fmaxf(sqrtf(red[0]), 1e-12f);
    #pragma unroll
    for (int i = 0; i < 4; i++) {
        int d = tid + i * 128;
        float nv = v[i] * inv;
        g_xn[(size_t)row * D_SZ + d] = nv;
        g_xh[(size_t)row * D_SZ + d] = __float2half_rn(nv);
    }
    if (tid == 0) {
        g_rowsum[row] = 0.f;
        g_flags[row < NTILES_N ? row : 0] = 0;
        if (row + 512 < NTILES_N) g_flags[row + 512] = 0;
        if (row == 0) out[0] = 0.f;
    }
}

// ---------------------------------------------------------------------------
// Kernel 2: persistent fused GEMM. Grid 148 = 4 m-tiles x 37 stripes.
// Stripe s owns tiles n = s, s+37, ... Each quad CTA converts 1/4 (32 rows)
// of the NEXT tile (raw fp32 -> raw fp16 + winv) interleaved with the k-loop,
// gated by a 4-count flag per tile. Epilogue applies winv (deferred norm).
// ---------------------------------------------------------------------------
__global__ void __launch_bounds__(256, 1) gemm_persistent(const float* __restrict__ w) {
    extern __shared__ __align__(16) char smem[];
    const int tid = threadIdx.x;
    const int warp = tid >> 5;
    const int lane = tid & 31;
    const int wm = warp & 1;
    const int wn = warp >> 1;
    const int m = blockIdx.x & 3;
    const int s = blockIdx.x >> 2;          // 0..36
    const int m0 = m * BM;
    const uint32_t sb = smem_u32(smem);
    float* swinv = reinterpret_cast<float*>(smem + WINV_OFF);

    const __half* srcA = g_xh + (size_t)m0 * D_SZ;

    // conversion identity: this CTA converts rows [m*32, m*32+32) of a tile;
    // thread t -> row m*32 + (t>>3), float cols [(t&7)*64, +64)
    const int crow = m * 32 + (tid >> 3);
    const int ccol = (tid & 7) * 64;

    // ---- prologue: convert quarter of first tile s ----
    {
        const int grow = s * BN + crow;
        float ss = 0.f;
        uint2* dst = reinterpret_cast<uint2*>(g_wh + (size_t)grow * D_SZ + ccol);
        if (grow < C_SZ) {
            const float4* src = reinterpret_cast<const float4*>(w + (size_t)grow * D_SZ + ccol);
            #pragma unroll 4
            for (int j = 0; j < 16; j++) {
                float4 v = src[j];
                ss += v.x * v.x + v.y * v.y + v.z * v.z + v.w * v.w;
                dst[j] = pack4h(v);
            }
        } else {
            uint2 z = make_uint2(0u, 0u);
            #pragma unroll 4
            for (int j = 0; j < 16; j++) dst[j] = z;
        }
        ss += __shfl_xor_sync(0xffffffffu, ss, 1);
        ss += __shfl_xor_sync(0xffffffffu, ss, 2);
        ss += __shfl_xor_sync(0xffffffffu, ss, 4);
        if ((tid & 7) == 0)
            g_winv[grow] = (grow < C_SZ && ss > 0.f) ? rsqrtf(ss) * S_SCALE : 0.f;
        __threadfence();
        __syncthreads();
        if (tid == 0) atomicAdd(&g_flags[s], 1);
    }

    const int lrow = lane & 15;
    const int lcol = (lane >> 4) * 8;

    for (int n = s; n < NTILES_N; n += NSTRIPE) {
        const int n_next = n + NSTRIPE;
        const bool has_next = (n_next < NTILES_N);

        // ---- wait for tile n fully converted (4 quarters) ----
        if (tid == 0) {
            int v;
            do {
                asm volatile("ld.acquire.gpu.global.s32 %0, [%1];"
                             : "=r"(v) : "l"(g_flags + n) : "memory");
                if (v < 4) __nanosleep(32);
            } while (v < 4);
        }
        __syncthreads();

        if (tid < BN) swinv[tid] = g_winv[n * BN + tid];

        const __half* srcB = g_wh + (size_t)n * BN * D_SZ;

        // conversion state for tile n_next
        const int cgrow = n_next * BN + crow;
        const bool cvalid = has_next && (cgrow < C_SZ);
        const float4* csrc = reinterpret_cast<const float4*>(w + (size_t)cgrow * D_SZ + ccol);
        uint2* cdst = reinterpret_cast<uint2*>(g_wh + (size_t)cgrow * D_SZ + ccol);
        float cssq = 0.f;

        uint32_t acc[4][4][2];
        #pragma unroll
        for (int a = 0; a < 4; a++)
            #pragma unroll
            for (int b = 0; b < 4; b++) { acc[a][b][0] = 0u; acc[a][b][1] = 0u; }

        auto load_stage = [&](int stage, int k0) {
            const uint32_t dst = sb + (uint32_t)stage * STAGE_B;
            #pragma unroll
            for (int j = 0; j < 8; j++) {
                int idx = tid + 256 * j;
                int row = (idx >> 3) & 127;
                int piece = idx & 7;
                uint32_t doff = (uint32_t)(row * (PITCH * 2) + piece * 16);
                if (idx < 1024)
                    cp16(dst + doff, srcA + (size_t)row * D_SZ + k0 + piece * 8);
                else
                    cp16(dst + B_PART + doff, srcB + (size_t)row * D_SZ + k0 + piece * 8);
            }
        };

        load_stage(0, 0);
        CP_COMMIT();
        load_stage(1, BK);
        CP_COMMIT();

        for (int k = 0; k < NK; k++) {
            if (k == NK - 1) { CP_WAIT(0); } else { CP_WAIT(1); }
            __syncthreads();

            const uint32_t aoff = sb + (uint32_t)(k % NSTAGE) * STAGE_B;
            const uint32_t boff = aoff + B_PART;
            #pragma unroll
            for (int kk = 0; kk < BK; kk += 16) {
                uint32_t af[4][4], bf[2][4];
                #pragma unroll
                for (int mt = 0; mt < 4; mt++)
                    ldsm4(af[mt], aoff + (uint32_t)((wm * 64 + mt * 16 + lrow) * PITCH + kk + lcol) * 2);
                #pragma unroll
                for (int nt2 = 0; nt2 < 2; nt2++)
                    ldsm4(bf[nt2], boff + (uint32_t)((wn * 32 + nt2 * 16 + lrow) * PITCH + kk + lcol) * 2);
                #pragma unroll
                for (int mt = 0; mt < 4; mt++) {
                    #pragma unroll
                    for (int nt = 0; nt < 4; nt++) {
                        const uint32_t* bb = bf[nt >> 1];
                        uint32_t b0 = (nt & 1) ? bb[1] : bb[0];
                        uint32_t b1 = (nt & 1) ? bb[3] : bb[2];
                        mma16816h(acc[mt][nt], af[mt], b0, b1);
                    }
                }
            }

            // background conversion: 2 of 16 chunks of next tile per k-step
            if (has_next) {
                #pragma unroll
                for (int jj = 0; jj < 2; jj++) {
                    int j = k * 2 + jj;
                    if (cvalid) {
                        float4 v = csrc[j];
                        cssq += v.x * v.x + v.y * v.y + v.z * v.z + v.w * v.w;
                        cdst[j] = pack4h(v);
                    } else {
                        cdst[j] = make_uint2(0u, 0u);
                    }
                }
            }

            __syncthreads();   // stage k fully consumed before refill

            if (k + 2 < NK) {
                load_stage((k + 2) % NSTAGE, (k + 2) * BK);
                CP_COMMIT();
            }
        }

        // ---- publish next tile's quarter ----
        if (has_next) {
            float ssr = cssq;
            ssr += __shfl_xor_sync(0xffffffffu, ssr, 1);
            ssr += __shfl_xor_sync(0xffffffffu, ssr, 2);
            ssr += __shfl_xor_sync(0xffffffffu, ssr, 4);
            if ((tid & 7) == 0)
                g_winv[cgrow] = (cvalid && ssr > 0.f) ? rsqrtf(ssr) * S_SCALE : 0.f;
            __threadfence();
            __syncthreads();
            if (tid == 0) atomicAdd(&g_flags[n_next], 1);
        }

        // ---- epilogue: logit = acc * winv30; exp-sum per row -> atomic -----
        const bool edge = (n == NTILES_N - 1);
        const int rbase = m0 + wm * 64 + (lane >> 2);
        const int cl = wn * 32 + 2 * (lane & 3);
        const int gc = n * BN + cl;

        #pragma unroll
        for (int mt = 0; mt < 4; mt++) {
            float es0 = 0.f, es1 = 0.f;
            #pragma unroll
            for (int nt = 0; nt < 4; nt++) {
                const int c0 = cl + nt * 8;
                const float s0 = swinv[c0], s1 = swinv[c0 + 1];
                float2 f01 = __half22float2(*reinterpret_cast<__half2*>(&acc[mt][nt][0]));
                float2 f23 = __half22float2(*reinterpret_cast<__half2*>(&acc[mt][nt][1]));
                if (!edge) {
                    es0 += __expf(fmaf(f01.x, s0, -LMAX));
                    es0 += __expf(fmaf(f01.y, s1, -LMAX));
                    es1 += __expf(fmaf(f23.x, s0, -LMAX));
                    es1 += __expf(fmaf(f23.y, s1, -LMAX));
                } else {
                    if (gc + nt * 8 < C_SZ)     { es0 += __expf(fmaf(f01.x, s0, -LMAX));
                                                  es1 += __expf(fmaf(f23.x, s0, -LMAX)); }
                    if (gc + nt * 8 + 1 < C_SZ) { es0 += __expf(fmaf(f01.y, s1, -LMAX));
                                                  es1 += __expf(fmaf(f23.y, s1, -LMAX)); }
                }
            }
            es0 += __shfl_xor_sync(0xffffffffu, es0, 1);
            es0 += __shfl_xor_sync(0xffffffffu, es0, 2);
            es1 += __shfl_xor_sync(0xffffffffu, es1, 1);
            es1 += __shfl_xor_sync(0xffffffffu, es1, 2);
            if ((lane & 3) == 0) {
                atomicAdd(&g_rowsum[rbase + mt * 16], es0);
                atomicAdd(&g_rowsum[rbase + mt * 16 + 8], es1);
            }
        }
    }
}

// ---------------------------------------------------------------------------
// Kernel 3: finalize — exact fp32 target dot + target norm, margin swap, nll;
// atomic mean accumulation into out[0] (zeroed by xnorm).
// ---------------------------------------------------------------------------
__global__ void finalize_kernel(const float* __restrict__ w,
                                const int* __restrict__ tgt,
                                float* __restrict__ out) {
    const int b = blockIdx.x;
    const int tid = threadIdx.x;   // 256
    __shared__ float sd[256], sn[256];

    const int t = tgt[b];
    const float* wr = w + (size_t)t * D_SZ;
    const float* xr = g_xn + (size_t)b * D_SZ;
    float w0 = wr[tid], w1 = wr[tid + 256];
    sd[tid] = xr[tid] * w0 + xr[tid + 256] * w1;
    sn[tid] = w0 * w0 + w1 * w1;
    __syncthreads();
    #pragma unroll
    for (int off = 128; off > 0; off >>= 1) {
        if (tid < off) { sd[tid] += sd[tid + off]; sn[tid] += sn[tid + off]; }
        __syncthreads();
    }

    if (tid == 0) {
        float winv = 1.f / fmaxf(sqrtf(sn[0]), 1e-12f);
        float cosv = sd[0] * winv;
        float sinv = sqrtf(fmaxf(1.f - cosv * cosv, 0.f));
        float phi = cosv * COS_M - sinv * SIN_M;
        float adj = (cosv > 0.f) ? phi : cosv;          // easy margin
        float lt = S_SCALE * adj;
        float lo = S_SCALE * cosv;
        float s2 = g_rowsum[b] - expf(lo - LMAX) + expf(lt - LMAX);
        float nll = LMAX + logf(s2) - lt;
        atomicAdd(out, nll * (1.f / (float)B_SZ));
    }
}

// ---------------------------------------------------------------------------
extern "C" void kernel_launch(void* const* d_in, const int* in_sizes, int n_in,
                              void* d_out, int out_size) {
    const float* x = (const float*)d_in[0];
    const float* w = (const float*)d_in[1];
    const int* tgt = (const int*)d_in[2];
    float* out = (float*)d_out;

    cudaFuncSetAttribute(gemm_persistent,
                         cudaFuncAttributeMaxDynamicSharedMemorySize, SMEM_BYTES);

    xnorm_kernel<<<B_SZ, 128>>>(x, out);
    gemm_persistent<<<4 * NSTRIPE, 256, SMEM_BYTES>>>(w);
    finalize_kernel<<<B_SZ, 256>>>(w, tgt, out);
}

// round 16
// speedup vs baseline: 1.8961x; 1.8961x over previous
#include <cuda_runtime.h>
#include <cuda_fp16.h>
#include <math.h>
#include <stdint.h>

#define B_SZ 512
#define D_SZ 512
#define C_SZ 100000
#define BN 128
#define BM 128
#define BK 64
#define NK 8                       // 512/64
#define NSTAGE 2
#define NTILES_N 782               // ceil(100000/128)
#define C_PAD (NTILES_N * BN)      // 100096 (pad rows stay zero)
#define PITCH 72                   // halves per smem row (144 B) — conflict-free ldsm
#define STAGE_B (2 * 128 * PITCH * 2)      // A half + B half = 36864 B
#define B_PART  (128 * PITCH * 2)          // 18432
#define SMEM_BYTES (NSTAGE * STAGE_B)      // 73728 -> 2 CTAs/SM fit
#define S_SCALE 30.0f
#define LMAX 31.0f
#define COS_M 0.8775825618903728f
#define SIN_M 0.47942553860420300f

// ---------------- static device scratch -------------------------------------
__device__ __half g_wh[(size_t)C_PAD * D_SZ];   // normalized fp16 w (pads stay 0)
__device__ __half g_xh[B_SZ * D_SZ];            // normalized fp16 x
__device__ float g_xn[B_SZ * D_SZ];
__device__ float g_rowsum[B_SZ];

// ---------------- PTX helpers ------------------------------------------------
__device__ __forceinline__ uint32_t smem_u32(const void* p) {
    uint32_t a;
    asm("{ .reg .u64 t; cvta.to.shared.u64 t, %1; cvt.u32.u64 %0, t; }" : "=r"(a) : "l"(p));
    return a;
}
__device__ __forceinline__ void cp16(uint32_t dst, const void* src) {
    asm volatile("cp.async.cg.shared.global [%0], [%1], 16;" :: "r"(dst), "l"(src));
}
#define CP_COMMIT() asm volatile("cp.async.commit_group;" ::: "memory")
#define CP_WAIT(n)  asm volatile("cp.async.wait_group %0;" :: "n"(n) : "memory")

__device__ __forceinline__ void ldsm4(uint32_t* r, uint32_t addr) {
    asm volatile("ldmatrix.sync.aligned.m8n8.x4.shared.b16 {%0,%1,%2,%3}, [%4];"
        : "=r"(r[0]), "=r"(r[1]), "=r"(r[2]), "=r"(r[3]) : "r"(addr));
}
// fp16 inputs, fp16 accumulators
__device__ __forceinline__ void mma16816h(uint32_t* d, const uint32_t* a, uint32_t b0, uint32_t b1) {
    asm volatile(
        "mma.sync.aligned.m16n8k16.row.col.f16.f16.f16.f16 "
        "{%0,%1}, {%2,%3,%4,%5}, {%6,%7}, {%0,%1};"
        : "+r"(d[0]), "+r"(d[1])
        : "r"(a[0]), "r"(a[1]), "r"(a[2]), "r"(a[3]), "r"(b0), "r"(b1));
}

// ---------------------------------------------------------------------------
// Kernel 1: normalize x rows -> g_xn (fp32) + g_xh (fp16); zero g_rowsum/out
// ---------------------------------------------------------------------------
__global__ void xnorm_kernel(const float* __restrict__ x, float* __restrict__ out) {
    const int row = blockIdx.x;
    const int tid = threadIdx.x;   // 128
    const float* xr = x + (size_t)row * D_SZ;

    float ss = 0.f;
    float v[4];
    #pragma unroll
    for (int i = 0; i < 4; i++) { v[i] = xr[tid + i * 128]; ss += v[i] * v[i]; }
    __shared__ float red[128];
    red[tid] = ss;
    __syncthreads();
    #pragma unroll
    for (int off = 64; off > 0; off >>= 1) {
        if (tid < off) red[tid] += red[tid + off];
        __syncthreads();
    }
    const float inv = 1.f / fmaxf(sqrtf(red[0]), 1e-12f);
    #pragma unroll
    for (int i = 0; i < 4; i++) {
        int d = tid + i * 128;
        float nv = v[i] * inv;
        g_xn[(size_t)row * D_SZ + d] = nv;
        g_xh[(size_t)row * D_SZ + d] = __float2half_rn(nv);
    }
    if (tid == 0) {
        g_rowsum[row] = 0.f;
        if (row == 0) out[0] = 0.f;
    }
}

// ---------------------------------------------------------------------------
// Kernel 2: normalize weight rows + convert to fp16 (one warp per row)
// ---------------------------------------------------------------------------
__global__ void wconv_kernel(const float* __restrict__ w) {
    const int warp = threadIdx.x >> 5;
    const int lane = threadIdx.x & 31;
    const int c = blockIdx.x * 8 + warp;       // grid 12500 -> 100000 rows
    const float4* wr = reinterpret_cast<const float4*>(w + (size_t)c * D_SZ);

    float4 v[4];
    float ss = 0.f;
    #pragma unroll
    for (int i = 0; i < 4; i++) {
        v[i] = wr[lane + i * 32];
        ss += v[i].x * v[i].x + v[i].y * v[i].y + v[i].z * v[i].z + v[i].w * v[i].w;
    }
    #pragma unroll
    for (int m = 16; m > 0; m >>= 1)
        ss += __shfl_xor_sync(0xffffffffu, ss, m);
    const float inv = 1.f / fmaxf(sqrtf(ss), 1e-12f);

    uint2* dst = reinterpret_cast<uint2*>(g_wh + (size_t)c * D_SZ);
    #pragma unroll
    for (int i = 0; i < 4; i++) {
        __half2 p0 = __floats2half2_rn(v[i].x * inv, v[i].y * inv);
        __half2 p1 = __floats2half2_rn(v[i].z * inv, v[i].w * inv);
        uint2 o;
        o.x = *reinterpret_cast<uint32_t*>(&p0);
        o.y = *reinterpret_cast<uint32_t*>(&p1);
        dst[lane + i * 32] = o;
    }
}

// ---------------------------------------------------------------------------
// Kernel 3: fused HMMA GEMM (fp16 in/acc) + streaming exp-sum epilogue.
// CTA 128x128xK512. 2-stage cp.async ring (73.7 KB smem) so TWO CTAs
// co-reside per SM and overlap each other's barrier/fill/epilogue bubbles.
// Grid (m=4, n=782) so 4 CTAs share each B tile via L2.
// ---------------------------------------------------------------------------
__global__ void __launch_bounds__(256, 2) gemm_fused_kernel() {
    extern __shared__ __align__(16) char smem[];
    const int tid = threadIdx.x;
    const int warp = tid >> 5;
    const int lane = tid & 31;
    const int wm = warp & 1;
    const int wn = warp >> 1;
    const int m0 = blockIdx.x * BM;
    const int n0 = blockIdx.y * BN;
    const uint32_t sb = smem_u32(smem);

    const __half* srcA = g_xh + (size_t)m0 * D_SZ;
    const __half* srcB = g_wh + (size_t)n0 * D_SZ;

    uint32_t acc[4][4][2];
    #pragma unroll
    for (int a = 0; a < 4; a++)
        #pragma unroll
        for (int b = 0; b < 4; b++) { acc[a][b][0] = 0u; acc[a][b][1] = 0u; }

    // stage loader: 2048 cp16 (A: 128x64 halves, B: 128x64 halves), 8/thread
    auto load_stage = [&](int stage, int k0) {
        const uint32_t dst = sb + (uint32_t)stage * STAGE_B;
        #pragma unroll
        for (int j = 0; j < 8; j++) {
            int idx = tid + 256 * j;            // 0..2047
            int row = (idx >> 3) & 127;
            int piece = idx & 7;
            uint32_t doff = (uint32_t)(row * (PITCH * 2) + piece * 16);
            if (idx < 1024)
                cp16(dst + doff, srcA + (size_t)row * D_SZ + k0 + piece * 8);
            else
                cp16(dst + B_PART + doff, srcB + (size_t)row * D_SZ + k0 + piece * 8);
        }
    };

    load_stage(0, 0);
    CP_COMMIT();
    load_stage(1, BK);
    CP_COMMIT();

    const int lrow = lane & 15;
    const int lcol = (lane >> 4) * 8;

    // double-buffered fragments
    uint32_t af[2][4][4], bf[2][2][4];
    auto ldfrags = [&](uint32_t aoff, uint32_t boff, int kk, int buf) {
        #pragma unroll
        for (int mt = 0; mt < 4; mt++)
            ldsm4(af[buf][mt], aoff + (uint32_t)((wm * 64 + mt * 16 + lrow) * PITCH + kk + lcol) * 2);
        #pragma unroll
        for (int nt2 = 0; nt2 < 2; nt2++)
            ldsm4(bf[buf][nt2], boff + (uint32_t)((wn * 32 + nt2 * 16 + lrow) * PITCH + kk + lcol) * 2);
    };

    for (int k = 0; k < NK; k++) {
        if (k == NK - 1) { CP_WAIT(0); } else { CP_WAIT(1); }
        __syncthreads();

        const uint32_t aoff = sb + (uint32_t)(k % NSTAGE) * STAGE_B;
        const uint32_t boff = aoff + B_PART;

        ldfrags(aoff, boff, 0, 0);
        #pragma unroll
        for (int c4 = 0; c4 < 4; c4++) {           // kk = c4*16
            const int cur = c4 & 1;
            if (c4 < 3) ldfrags(aoff, boff, (c4 + 1) * 16, cur ^ 1);
            #pragma unroll
            for (int mt = 0; mt < 4; mt++) {
                #pragma unroll
                for (int nt = 0; nt < 4; nt++) {
                    const uint32_t* bb = bf[cur][nt >> 1];
                    uint32_t b0 = (nt & 1) ? bb[1] : bb[0];
                    uint32_t b1 = (nt & 1) ? bb[3] : bb[2];
                    mma16816h(acc[mt][nt], af[cur][mt], b0, b1);
                }
            }
        }
        __syncthreads();   // stage k fully consumed before it is refilled

        if (k + 2 < NK) {
            load_stage((k + 2) % NSTAGE, (k + 2) * BK);
            CP_COMMIT();
        }
    }

    // ---- epilogue: exp-sum per batch row, atomic into g_rowsum -------------
    const bool edge = (n0 + BN > C_SZ);
    const int rbase = m0 + wm * 64 + (lane >> 2);
    const int cbase = n0 + wn * 32 + 2 * (lane & 3);

    #pragma unroll
    for (int mt = 0; mt < 4; mt++) {
        float es0 = 0.f, es1 = 0.f;
        #pragma unroll
        for (int nt = 0; nt < 4; nt++) {
            const int c0 = cbase + nt * 8;
            float2 f01 = __half22float2(*reinterpret_cast<__half2*>(&acc[mt][nt][0]));
            float2 f23 = __half22float2(*reinterpret_cast<__half2*>(&acc[mt][nt][1]));
            if (!edge) {
                es0 += __expf(fmaf(f01.x, S_SCALE, -LMAX));
                es0 += __expf(fmaf(f01.y, S_SCALE, -LMAX));
                es1 += __expf(fmaf(f23.x, S_SCALE, -LMAX));
                es1 += __expf(fmaf(f23.y, S_SCALE, -LMAX));
            } else {
                if (c0 < C_SZ)     { es0 += __expf(fmaf(f01.x, S_SCALE, -LMAX));
                                     es1 += __expf(fmaf(f23.x, S_SCALE, -LMAX)); }
                if (c0 + 1 < C_SZ) { es0 += __expf(fmaf(f01.y, S_SCALE, -LMAX));
                                     es1 += __expf(fmaf(f23.y, S_SCALE, -LMAX)); }
            }
        }
        es0 += __shfl_xor_sync(0xffffffffu, es0, 1);
        es0 += __shfl_xor_sync(0xffffffffu, es0, 2);
        es1 += __shfl_xor_sync(0xffffffffu, es1, 1);
        es1 += __shfl_xor_sync(0xffffffffu, es1, 2);
        if ((lane & 3) == 0) {
            atomicAdd(&g_rowsum[rbase + mt * 16], es0);
            atomicAdd(&g_rowsum[rbase + mt * 16 + 8], es1);
        }
    }
}

// ---------------------------------------------------------------------------
// Kernel 4: finalize — exact fp32 target dot + target norm, margin swap, nll;
// atomic mean accumulation into out[0] (zeroed by xnorm).
// ---------------------------------------------------------------------------
__global__ void finalize_kernel(const float* __restrict__ w,
                                const int* __restrict__ tgt,
                                float* __restrict__ out) {
    const int b = blockIdx.x;
    const int tid = threadIdx.x;   // 256
    __shared__ float sd[256], sn[256];

    const int t = tgt[b];
    const float* wr = w + (size_t)t * D_SZ;
    const float* xr = g_xn + (size_t)b * D_SZ;
    float w0 = wr[tid], w1 = wr[tid + 256];
    sd[tid] = xr[tid] * w0 + xr[tid + 256] * w1;
    sn[tid] = w0 * w0 + w1 * w1;
    __syncthreads();
    #pragma unroll
    for (int off = 128; off > 0; off >>= 1) {
        if (tid < off) { sd[tid] += sd[tid + off]; sn[tid] += sn[tid + off]; }
        __syncthreads();
    }

    if (tid == 0) {
        float winv = 1.f / fmaxf(sqrtf(sn[0]), 1e-12f);
        float cosv = sd[0] * winv;
        float sinv = sqrtf(fmaxf(1.f - cosv * cosv, 0.f));
        float phi = cosv * COS_M - sinv * SIN_M;
        float adj = (cosv > 0.f) ? phi : cosv;          // easy margin
        float lt = S_SCALE * adj;
        float lo = S_SCALE * cosv;
        float s2 = g_rowsum[b] - expf(lo - LMAX) + expf(lt - LMAX);
        float nll = LMAX + logf(s2) - lt;
        atomicAdd(out, nll * (1.f / (float)B_SZ));
    }
}

// ---------------------------------------------------------------------------
extern "C" void kernel_launch(void* const* d_in, const int* in_sizes, int n_in,
                              void* d_out, int out_size) {
    const float* x = (const float*)d_in[0];
    const float* w = (const float*)d_in[1];
    const int* tgt = (const int*)d_in[2];
    float* out = (float*)d_out;

    cudaFuncSetAttribute(gemm_fused_kernel,
                         cudaFuncAttributeMaxDynamicSharedMemorySize, SMEM_BYTES);

    xnorm_kernel<<<B_SZ, 128>>>(x, out);
    wconv_kernel<<<C_SZ / 8, 256>>>(w);
    dim3 grid(B_SZ / BM, NTILES_N);
    gemm_fused_kernel<<<grid, 256, SMEM_BYTES>>>();
    finalize_kernel<<<B_SZ, 256>>>(w, tgt, out);
}

// round 17
// speedup vs baseline: 1.9726x; 1.0404x over previous
#include <cuda_runtime.h>
#include <cuda_fp16.h>
#include <math.h>
#include <stdint.h>

#define B_SZ 512
#define D_SZ 512
#define C_SZ 100000
#define BN 128
#define BM 128
#define BK 64
#define NK 8                       // 512/64
#define NSTAGE 3
#define NTILES_N 782               // ceil(100000/128)
#define C_PAD (NTILES_N * BN)      // 100096 (pad rows stay zero)
#define PITCH 72                   // halves per smem row (144 B) — conflict-free ldsm
#define STAGE_B (2 * 128 * PITCH * 2)      // A half + B half = 36864 B
#define B_PART  (128 * PITCH * 2)          // 18432
#define SMEM_BYTES (NSTAGE * STAGE_B)      // 110592
#define S_SCALE 30.0f
#define LOG2E30H 43.280851f        // 30*log2(e), rounded to fp16 in-kernel
#define LOG2E31F 44.723546267f     // 31*log2(e) (fp32 rescale offset)
#define COS_M 0.8775825618903728f
#define SIN_M 0.47942553860420300f
#define LMAX 31.0f

// ---------------- static device scratch -------------------------------------
__device__ __half g_wh[(size_t)C_PAD * D_SZ];   // normalized fp16 w (pads stay 0)
__device__ __half g_xh[B_SZ * D_SZ];            // normalized fp16 x
__device__ float g_xn[B_SZ * D_SZ];
__device__ float g_rowsum[B_SZ];

// ---------------- PTX helpers ------------------------------------------------
__device__ __forceinline__ uint32_t smem_u32(const void* p) {
    uint32_t a;
    asm("{ .reg .u64 t; cvta.to.shared.u64 t, %1; cvt.u32.u64 %0, t; }" : "=r"(a) : "l"(p));
    return a;
}
__device__ __forceinline__ void cp16(uint32_t dst, const void* src) {
    asm volatile("cp.async.cg.shared.global [%0], [%1], 16;" :: "r"(dst), "l"(src));
}
#define CP_COMMIT() asm volatile("cp.async.commit_group;" ::: "memory")
#define CP_WAIT(n)  asm volatile("cp.async.wait_group %0;" :: "n"(n) : "memory")

__device__ __forceinline__ void ldsm4(uint32_t* r, uint32_t addr) {
    asm volatile("ldmatrix.sync.aligned.m8n8.x4.shared.b16 {%0,%1,%2,%3}, [%4];"
        : "=r"(r[0]), "=r"(r[1]), "=r"(r[2]), "=r"(r[3]) : "r"(addr));
}
// fp16 inputs, fp16 accumulators
__device__ __forceinline__ void mma16816h(uint32_t* d, const uint32_t* a, uint32_t b0, uint32_t b1) {
    asm volatile(
        "mma.sync.aligned.m16n8k16.row.col.f16.f16.f16.f16 "
        "{%0,%1}, {%2,%3,%4,%5}, {%6,%7}, {%0,%1};"
        : "+r"(d[0]), "+r"(d[1])
        : "r"(a[0]), "r"(a[1]), "r"(a[2]), "r"(a[3]), "r"(b0), "r"(b1));
}

// ---------------------------------------------------------------------------
// Kernel 1: normalize x rows -> g_xn (fp32) + g_xh (fp16); zero g_rowsum/out
// ---------------------------------------------------------------------------
__global__ void xnorm_kernel(const float* __restrict__ x, float* __restrict__ out) {
    const int row = blockIdx.x;
    const int tid = threadIdx.x;   // 128
    const float* xr = x + (size_t)row * D_SZ;

    float ss = 0.f;
    float v[4];
    #pragma unroll
    for (int i = 0; i < 4; i++) { v[i] = xr[tid + i * 128]; ss += v[i] * v[i]; }
    __shared__ float red[128];
    red[tid] = ss;
    __syncthreads();
    #pragma unroll
    for (int off = 64; off > 0; off >>= 1) {
        if (tid < off) red[tid] += red[tid + off];
        __syncthreads();
    }
    const float inv = 1.f / fmaxf(sqrtf(red[0]), 1e-12f);
    #pragma unroll
    for (int i = 0; i < 4; i++) {
        int d = tid + i * 128;
        float nv = v[i] * inv;
        g_xn[(size_t)row * D_SZ + d] = nv;
        g_xh[(size_t)row * D_SZ + d] = __float2half_rn(nv);
    }
    if (tid == 0) {
        g_rowsum[row] = 0.f;
        if (row == 0) out[0] = 0.f;
    }
}

// ---------------------------------------------------------------------------
// Kernel 2: normalize weight rows + convert to fp16 (one warp per row)
// ---------------------------------------------------------------------------
__global__ void wconv_kernel(const float* __restrict__ w) {
    const int warp = threadIdx.x >> 5;
    const int lane = threadIdx.x & 31;
    const int c = blockIdx.x * 8 + warp;       // grid 12500 -> 100000 rows
    const float4* wr = reinterpret_cast<const float4*>(w + (size_t)c * D_SZ);

    float4 v[4];
    float ss = 0.f;
    #pragma unroll
    for (int i = 0; i < 4; i++) {
        v[i] = wr[lane + i * 32];
        ss += v[i].x * v[i].x + v[i].y * v[i].y + v[i].z * v[i].z + v[i].w * v[i].w;
    }
    #pragma unroll
    for (int m = 16; m > 0; m >>= 1)
        ss += __shfl_xor_sync(0xffffffffu, ss, m);
    const float inv = 1.f / fmaxf(sqrtf(ss), 1e-12f);

    uint2* dst = reinterpret_cast<uint2*>(g_wh + (size_t)c * D_SZ);
    #pragma unroll
    for (int i = 0; i < 4; i++) {
        __half2 p0 = __floats2half2_rn(v[i].x * inv, v[i].y * inv);
        __half2 p1 = __floats2half2_rn(v[i].z * inv, v[i].w * inv);
        uint2 o;
        o.x = *reinterpret_cast<uint32_t*>(&p0);
        o.y = *reinterpret_cast<uint32_t*>(&p1);
        dst[lane + i * 32] = o;
    }
}

// ---------------------------------------------------------------------------
// Kernel 3: fused HMMA GEMM (fp16 in/acc, R12 pipeline) + fp16x2-exp2 epilogue:
// per-thread log2-domain max-shift, h2exp2 (half the MUFU ops of __expf),
// fp16 pair-sums, single fp32 rescale to the global -31 offset, atomicAdd.
// ---------------------------------------------------------------------------
__global__ void __launch_bounds__(256, 1) gemm_fused_kernel() {
    extern __shared__ __align__(16) char smem[];
    const int tid = threadIdx.x;
    const int warp = tid >> 5;
    const int lane = tid & 31;
    const int wm = warp & 1;
    const int wn = warp >> 1;
    const int m0 = blockIdx.x * BM;
    const int n0 = blockIdx.y * BN;
    const uint32_t sb = smem_u32(smem);

    const __half* srcA = g_xh + (size_t)m0 * D_SZ;
    const __half* srcB = g_wh + (size_t)n0 * D_SZ;

    uint32_t acc[4][4][2];
    #pragma unroll
    for (int a = 0; a < 4; a++)
        #pragma unroll
        for (int b = 0; b < 4; b++) { acc[a][b][0] = 0u; acc[a][b][1] = 0u; }

    auto load_stage = [&](int stage, int k0) {
        const uint32_t dst = sb + (uint32_t)stage * STAGE_B;
        #pragma unroll
        for (int j = 0; j < 8; j++) {
            int idx = tid + 256 * j;            // 0..2047
            int row = (idx >> 3) & 127;
            int piece = idx & 7;
            uint32_t doff = (uint32_t)(row * (PITCH * 2) + piece * 16);
            if (idx < 1024)
                cp16(dst + doff, srcA + (size_t)row * D_SZ + k0 + piece * 8);
            else
                cp16(dst + B_PART + doff, srcB + (size_t)row * D_SZ + k0 + piece * 8);
        }
    };

    load_stage(0, 0);
    CP_COMMIT();
    load_stage(1, BK);
    CP_COMMIT();

    const int lrow = lane & 15;
    const int lcol = (lane >> 4) * 8;

    uint32_t af[2][4][4], bf[2][2][4];
    auto ldfrags = [&](uint32_t aoff, uint32_t boff, int kk, int buf) {
        #pragma unroll
        for (int mt = 0; mt < 4; mt++)
            ldsm4(af[buf][mt], aoff + (uint32_t)((wm * 64 + mt * 16 + lrow) * PITCH + kk + lcol) * 2);
        #pragma unroll
        for (int nt2 = 0; nt2 < 2; nt2++)
            ldsm4(bf[buf][nt2], boff + (uint32_t)((wn * 32 + nt2 * 16 + lrow) * PITCH + kk + lcol) * 2);
    };

    for (int k = 0; k < NK; k++) {
        if (k == NK - 1) { CP_WAIT(0); } else { CP_WAIT(1); }
        __syncthreads();

        const uint32_t aoff = sb + (uint32_t)(k % NSTAGE) * STAGE_B;
        const uint32_t boff = aoff + B_PART;

        ldfrags(aoff, boff, 0, 0);
        #pragma unroll
        for (int c4 = 0; c4 < 4; c4++) {
            const int cur = c4 & 1;
            if (c4 < 3) ldfrags(aoff, boff, (c4 + 1) * 16, cur ^ 1);
            #pragma unroll
            for (int mt = 0; mt < 4; mt++) {
                #pragma unroll
                for (int nt = 0; nt < 4; nt++) {
                    const uint32_t* bb = bf[cur][nt >> 1];
                    uint32_t b0 = (nt & 1) ? bb[1] : bb[0];
                    uint32_t b1 = (nt & 1) ? bb[3] : bb[2];
                    mma16816h(acc[mt][nt], af[cur][mt], b0, b1);
                }
            }
        }
        __syncthreads();

        if (k + 2 < NK) {
            load_stage((k + 2) % NSTAGE, (k + 2) * BK);
            CP_COMMIT();
        }
    }

    // ---- epilogue (fp16x2 exp2) --------------------------------------------
    const bool edge = (n0 + BN > C_SZ);
    const int rbase = m0 + wm * 64 + (lane >> 2);
    const int cbase = n0 + wn * 32 + 2 * (lane & 3);

    // t = cos * 30*log2(e), in-place over acc; mask invalid classes to -inf
    const __half2 K2 = __float2half2_rn(LOG2E30H);
    const __half NINF = __ushort_as_half(0xFC00);
    __half2 l[4][4][2];
    #pragma unroll
    for (int mt = 0; mt < 4; mt++)
        #pragma unroll
        for (int nt = 0; nt < 4; nt++) {
            l[mt][nt][0] = __hmul2(*reinterpret_cast<__half2*>(&acc[mt][nt][0]), K2);
            l[mt][nt][1] = __hmul2(*reinterpret_cast<__half2*>(&acc[mt][nt][1]), K2);
            if (edge) {
                const int c0 = cbase + nt * 8;
                if (c0 >= C_SZ)     { l[mt][nt][0].x = NINF; l[mt][nt][1].x = NINF; }
                if (c0 + 1 >= C_SZ) { l[mt][nt][0].y = NINF; l[mt][nt][1].y = NINF; }
            }
        }

    // per-thread max (clamped to -60 so all-masked threads stay finite)
    __half2 m2 = l[0][0][0];
    #pragma unroll
    for (int mt = 0; mt < 4; mt++)
        #pragma unroll
        for (int nt = 0; nt < 4; nt++) {
            m2 = __hmax2(m2, l[mt][nt][0]);
            m2 = __hmax2(m2, l[mt][nt][1]);
        }
    __half m = __hmax(__hmax(__low2half(m2), __high2half(m2)), __float2half(-60.f));
    const __half2 mm = __half2half2(m);
    const float scale = exp2f(__half2float(m) - LOG2E31F);

    // e = 2^(t - m); fp16 pair sums per (mt, row-half); rescale; reduce
    #pragma unroll
    for (int mt = 0; mt < 4; mt++) {
        __half2 s0 = h2exp2(__hsub2(l[mt][0][0], mm));
        __half2 s1 = h2exp2(__hsub2(l[mt][0][1], mm));
        #pragma unroll
        for (int nt = 1; nt < 4; nt++) {
            s0 = __hadd2(s0, h2exp2(__hsub2(l[mt][nt][0], mm)));
            s1 = __hadd2(s1, h2exp2(__hsub2(l[mt][nt][1], mm)));
        }
        float2 f0 = __half22float2(s0);
        float2 f1 = __half22float2(s1);
        float es0 = (f0.x + f0.y) * scale;
        float es1 = (f1.x + f1.y) * scale;

        es0 += __shfl_xor_sync(0xffffffffu, es0, 1);
        es0 += __shfl_xor_sync(0xffffffffu, es0, 2);
        es1 += __shfl_xor_sync(0xffffffffu, es1, 1);
        es1 += __shfl_xor_sync(0xffffffffu, es1, 2);
        if ((lane & 3) == 0) {
            atomicAdd(&g_rowsum[rbase + mt * 16], es0);
            atomicAdd(&g_rowsum[rbase + mt * 16 + 8], es1);
        }
    }
}

// ---------------------------------------------------------------------------
// Kernel 4: finalize — exact fp32 target dot + target norm, margin swap, nll;
// atomic mean accumulation into out[0] (zeroed by xnorm).
// ---------------------------------------------------------------------------
__global__ void finalize_kernel(const float* __restrict__ w,
                                const int* __restrict__ tgt,
                                float* __restrict__ out) {
    const int b = blockIdx.x;
    const int tid = threadIdx.x;   // 256
    __shared__ float sd[256], sn[256];

    const int t = tgt[b];
    const float* wr = w + (size_t)t * D_SZ;
    const float* xr = g_xn + (size_t)b * D_SZ;
    float w0 = wr[tid], w1 = wr[tid + 256];
    sd[tid] = xr[tid] * w0 + xr[tid + 256] * w1;
    sn[tid] = w0 * w0 + w1 * w1;
    __syncthreads();
    #pragma unroll
    for (int off = 128; off > 0; off >>= 1) {
        if (tid < off) { sd[tid] += sd[tid + off]; sn[tid] += sn[tid + off]; }
        __syncthreads();
    }

    if (tid == 0) {
        float winv = 1.f / fmaxf(sqrtf(sn[0]), 1e-12f);
        float cosv = sd[0] * winv;
        float sinv = sqrtf(fmaxf(1.f - cosv * cosv, 0.f));
        float phi = cosv * COS_M - sinv * SIN_M;
        float adj = (cosv > 0.f) ? phi : cosv;          // easy margin
        float lt = S_SCALE * adj;
        float lo = S_SCALE * cosv;
        float s2 = g_rowsum[b] - expf(lo - LMAX) + expf(lt - LMAX);
        float nll = LMAX + logf(s2) - lt;
        atomicAdd(out, nll * (1.f / (float)B_SZ));
    }
}

// ---------------------------------------------------------------------------
extern "C" void kernel_launch(void* const* d_in, const int* in_sizes, int n_in,
                              void* d_out, int out_size) {
    const float* x = (const float*)d_in[0];
    const float* w = (const float*)d_in[1];
    const int* tgt = (const int*)d_in[2];
    float* out = (float*)d_out;

    cudaFuncSetAttribute(gemm_fused_kernel,
                         cudaFuncAttributeMaxDynamicSharedMemorySize, SMEM_BYTES);

    xnorm_kernel<<<B_SZ, 128>>>(x, out);
    wconv_kernel<<<C_SZ / 8, 256>>>(w);
    dim3 grid(B_SZ / BM, NTILES_N);
    gemm_fused_kernel<<<grid, 256, SMEM_BYTES>>>();
    finalize_kernel<<<B_SZ, 256>>>(w, tgt, out);
}